// round 1
// baseline (speedup 1.0000x reference)
#include <cuda_runtime.h>
#include <math.h>

// Problem constants
#define BB 2
#define TT 2048
#define CCH 512
#define HH 8
#define DD 64
#define NROWS (BB*TT)   // 4096
#define C3 (3*CCH)      // 1536

// ---------------- scratch (static __device__, per allocation rules) ----------------
__device__ float g_h  [NROWS*CCH];     // ln1 output
__device__ float g_qkv[NROWS*C3];      // qkv
__device__ float g_att[NROWS*CCH];     // attention output
__device__ float g_y  [NROWS*CCH];     // att + h@w_self
__device__ float g_y2 [NROWS*CCH];     // after proj
__device__ float g_h2 [NROWS*CCH];     // ln2 output
__device__ float g_fc [NROWS*4*CCH];   // gelu(fc)

// ---------------- LayerNorm: one block (128 thr) per row of 512 ----------------
__global__ __launch_bounds__(128) void ln_kernel(const float* __restrict__ x,
                                                 const float* __restrict__ g,
                                                 const float* __restrict__ bta,
                                                 float* __restrict__ out)
{
    int row = blockIdx.x;
    int t = threadIdx.x;                       // 0..127, 4 elems each
    const float4* xr = (const float4*)(x + (size_t)row * CCH);
    float4 v = xr[t];
    float s  = v.x + v.y + v.z + v.w;
    float s2 = v.x*v.x + v.y*v.y + v.z*v.z + v.w*v.w;
    #pragma unroll
    for (int o = 16; o; o >>= 1) {
        s  += __shfl_xor_sync(0xffffffffu, s,  o);
        s2 += __shfl_xor_sync(0xffffffffu, s2, o);
    }
    __shared__ float ss[4], ss2[4];
    int w = t >> 5, l = t & 31;
    if (l == 0) { ss[w] = s; ss2[w] = s2; }
    __syncthreads();
    s  = ss[0]  + ss[1]  + ss[2]  + ss[3];
    s2 = ss2[0] + ss2[1] + ss2[2] + ss2[3];
    float m   = s  * (1.0f/512.0f);
    float var = s2 * (1.0f/512.0f) - m*m;
    float r   = rsqrtf(var + 1e-5f);
    float4 gv = ((const float4*)g)[t];
    float4 bv = ((const float4*)bta)[t];
    float4 o4;
    o4.x = (v.x - m) * r * gv.x + bv.x;
    o4.y = (v.y - m) * r * gv.y + bv.y;
    o4.z = (v.z - m) * r * gv.z + bv.z;
    o4.w = (v.w - m) * r * gv.w + bv.w;
    ((float4*)(out + (size_t)row * CCH))[t] = o4;
}

// ---------------- SGEMM: C = A[MxK] @ W[KxN] + bias (+addend) (+gelu) ----------------
// BM=BN=128, BK=16, 256 threads, 8x8 per thread. All dims are exact multiples.
template<bool HAS_ADD, bool GELU_EPI>
__global__ __launch_bounds__(256) void sgemm_kernel(
    const float* __restrict__ A, const float* __restrict__ W,
    const float* __restrict__ bias, const float* __restrict__ addm,
    float* __restrict__ Cmat, int M, int N, int K)
{
    __shared__ float As[16*128];   // [k][m]
    __shared__ float Bs[16*128];   // [k][n]
    int bm = blockIdx.y, bn = blockIdx.x;
    int tid = threadIdx.x;
    int tx = tid & 15, ty = tid >> 4;
    float acc[8][8] = {};
    const float* Ab = A + (size_t)bm * 128 * K;
    const float* Wb = W + bn * 128;

    for (int k0 = 0; k0 < K; k0 += 16) {
        // load A tile 128x16, store transposed
        #pragma unroll
        for (int i = 0; i < 2; i++) {
            int j = tid + i*256;               // 0..511 float4s
            int row = j >> 2, cg = (j & 3) << 2;
            float4 v = *(const float4*)(Ab + (size_t)row * K + k0 + cg);
            As[(cg+0)*128 + row] = v.x;
            As[(cg+1)*128 + row] = v.y;
            As[(cg+2)*128 + row] = v.z;
            As[(cg+3)*128 + row] = v.w;
        }
        // load B tile 16x128 straight
        #pragma unroll
        for (int i = 0; i < 2; i++) {
            int j = tid + i*256;
            int row = j >> 5, cg = (j & 31) << 2;
            *(float4*)(Bs + row*128 + cg) =
                *(const float4*)(Wb + (size_t)(k0 + row) * N + cg);
        }
        __syncthreads();
        #pragma unroll
        for (int kk = 0; kk < 16; kk++) {
            float4 a0 = *(const float4*)(As + kk*128 + ty*8);
            float4 a1 = *(const float4*)(As + kk*128 + ty*8 + 4);
            float4 b0 = *(const float4*)(Bs + kk*128 + tx*8);
            float4 b1 = *(const float4*)(Bs + kk*128 + tx*8 + 4);
            float a[8] = {a0.x,a0.y,a0.z,a0.w,a1.x,a1.y,a1.z,a1.w};
            float b[8] = {b0.x,b0.y,b0.z,b0.w,b1.x,b1.y,b1.z,b1.w};
            #pragma unroll
            for (int i = 0; i < 8; i++)
                #pragma unroll
                for (int j = 0; j < 8; j++)
                    acc[i][j] = fmaf(a[i], b[j], acc[i][j]);
        }
        __syncthreads();
    }
    int r0 = bm*128 + ty*8, c0 = bn*128 + tx*8;
    float4 bsv0 = *(const float4*)(bias + c0);
    float4 bsv1 = *(const float4*)(bias + c0 + 4);
    float bvv[8] = {bsv0.x,bsv0.y,bsv0.z,bsv0.w,bsv1.x,bsv1.y,bsv1.z,bsv1.w};
    #pragma unroll
    for (int i = 0; i < 8; i++) {
        size_t ro = (size_t)(r0 + i) * N + c0;
        float v[8];
        #pragma unroll
        for (int j = 0; j < 8; j++) {
            float val = acc[i][j] + bvv[j];
            if (HAS_ADD) val += addm[ro + j];
            if (GELU_EPI) val = 0.5f * val * (1.0f + erff(val * 0.70710678118654752f));
            v[j] = val;
        }
        *(float4*)(Cmat + ro)     = make_float4(v[0],v[1],v[2],v[3]);
        *(float4*)(Cmat + ro + 4) = make_float4(v[4],v[5],v[6],v[7]);
    }
}

// ---------------- fast sigmoid: FMA-pipe only (no MUFU) ----------------
__device__ __forceinline__ float sigmoid_fast(float x) {
    // exp(-x) = 2^t, t = -x*log2(e), clamp: sigmoid indistinguishable beyond |x|~14
    float t = x * -1.4426950408889634f;
    t = fminf(fmaxf(t, -20.0f), 20.0f);
    float fi = floorf(t);
    float f  = t - fi;                 // [0,1)
    // 2^f Taylor deg-6 (rel err ~2e-5)
    float p = 1.5403530393e-4f;
    p = fmaf(p, f, 1.3333558146e-3f);
    p = fmaf(p, f, 9.6181291076e-3f);
    p = fmaf(p, f, 5.5504108664e-2f);
    p = fmaf(p, f, 2.4022650696e-1f);
    p = fmaf(p, f, 6.9314718056e-1f);
    p = fmaf(p, f, 1.0f);
    float r = __int_as_float(((int)fi + 127) << 23) * p;   // exp(-x)
    float a = 1.0f + r;
    // 1/a via bit-hack + 3 Newton iterations (rel err < 1e-7 on a in [1, 2^21])
    float y = __int_as_float(0x7EF127EA - __float_as_int(a));
    y = y * (2.0f - a * y);
    y = y * (2.0f - a * y);
    y = y * (2.0f - a * y);
    return y;
}

// ---------------- fused attention: y[b,t,h*D+d] = sum_s sigmoid(qk*s)*coulomb * v ----------------
// grid (T/64, B*H), 256 threads, 64x64 tiles over (t,s), D=64. Dyn smem 68 KB.
__global__ __launch_bounds__(256) void attn_kernel(const float* __restrict__ qkv,
                                                   const float* __restrict__ coul,
                                                   float* __restrict__ yatt)
{
    extern __shared__ float sm[];
    float* Qt = sm;              // [d][t] stride 68 (q pre-scaled)
    float* Kt = sm + 64*68;      // [d][s] stride 68
    float* Vs = sm + 2*64*68;    // [s][c] stride 68
    float* St = sm + 3*64*68;    // [t][s] stride 68

    int bh = blockIdx.y;
    int b = bh >> 3, h = bh & 7;
    int t0 = blockIdx.x * 64;
    int tid = threadIdx.x;
    int tx = tid & 15, ty = tid >> 4;
    int tr0 = ty * 4, sc0 = tx * 4;
    const float scale = 0.125f;    // 1/sqrt(64), exact power of two

    // load Q tile [64 t][64 d] -> transposed, pre-scaled
    const float* qb = qkv + (size_t)(b*TT + t0) * C3 + h*DD;
    #pragma unroll
    for (int i = 0; i < 4; i++) {
        int j = tid + i*256;
        int r = j >> 4, cg = (j & 15) << 2;
        float4 v = *(const float4*)(qb + (size_t)r * C3 + cg);
        Qt[(cg+0)*68 + r] = v.x * scale;
        Qt[(cg+1)*68 + r] = v.y * scale;
        Qt[(cg+2)*68 + r] = v.z * scale;
        Qt[(cg+3)*68 + r] = v.w * scale;
    }

    float yacc[4][4] = {};
    const float* cb = coul + (size_t)b * TT * TT;

    for (int s0 = 0; s0 < TT; s0 += 64) {
        __syncthreads();    // previous-iter consumers of Kt/Vs done (also covers Q stores)
        const float* kb = qkv + (size_t)(b*TT + s0) * C3 + CCH + h*DD;
        const float* vb = kb + CCH;
        #pragma unroll
        for (int i = 0; i < 4; i++) {
            int j = tid + i*256;
            int r = j >> 4, cg = (j & 15) << 2;
            float4 kv = *(const float4*)(kb + (size_t)r * C3 + cg);
            Kt[(cg+0)*68 + r] = kv.x;
            Kt[(cg+1)*68 + r] = kv.y;
            Kt[(cg+2)*68 + r] = kv.z;
            Kt[(cg+3)*68 + r] = kv.w;
            *(float4*)(Vs + r*68 + cg) = *(const float4*)(vb + (size_t)r * C3 + cg);
        }
        __syncthreads();

        // S = (Q*scale) @ K^T  (64x64x64)
        float sacc[4][4] = {};
        #pragma unroll 8
        for (int d = 0; d < 64; d++) {
            float4 av = *(const float4*)(Qt + d*68 + tr0);
            float4 bv = *(const float4*)(Kt + d*68 + sc0);
            float a[4] = {av.x, av.y, av.z, av.w};
            float bq[4] = {bv.x, bv.y, bv.z, bv.w};
            #pragma unroll
            for (int i = 0; i < 4; i++)
                #pragma unroll
                for (int j = 0; j < 4; j++)
                    sacc[i][j] = fmaf(a[i], bq[j], sacc[i][j]);
        }
        // apply sigmoid * coulomb, store to St[t][s]
        #pragma unroll
        for (int i = 0; i < 4; i++) {
            float4 cv = *(const float4*)(cb + (size_t)(t0 + tr0 + i) * TT + s0 + sc0);
            float4 sv;
            sv.x = sigmoid_fast(sacc[i][0]) * cv.x;
            sv.y = sigmoid_fast(sacc[i][1]) * cv.y;
            sv.z = sigmoid_fast(sacc[i][2]) * cv.z;
            sv.w = sigmoid_fast(sacc[i][3]) * cv.w;
            *(float4*)(St + (tr0 + i)*68 + sc0) = sv;
        }
        __syncthreads();

        // Y += S @ V (64x64x64)
        #pragma unroll 8
        for (int s = 0; s < 64; s++) {
            float a0 = St[(tr0+0)*68 + s];
            float a1 = St[(tr0+1)*68 + s];
            float a2 = St[(tr0+2)*68 + s];
            float a3 = St[(tr0+3)*68 + s];
            float4 vv = *(const float4*)(Vs + s*68 + sc0);
            yacc[0][0] = fmaf(a0, vv.x, yacc[0][0]);
            yacc[0][1] = fmaf(a0, vv.y, yacc[0][1]);
            yacc[0][2] = fmaf(a0, vv.z, yacc[0][2]);
            yacc[0][3] = fmaf(a0, vv.w, yacc[0][3]);
            yacc[1][0] = fmaf(a1, vv.x, yacc[1][0]);
            yacc[1][1] = fmaf(a1, vv.y, yacc[1][1]);
            yacc[1][2] = fmaf(a1, vv.z, yacc[1][2]);
            yacc[1][3] = fmaf(a1, vv.w, yacc[1][3]);
            yacc[2][0] = fmaf(a2, vv.x, yacc[2][0]);
            yacc[2][1] = fmaf(a2, vv.y, yacc[2][1]);
            yacc[2][2] = fmaf(a2, vv.z, yacc[2][2]);
            yacc[2][3] = fmaf(a2, vv.w, yacc[2][3]);
            yacc[3][0] = fmaf(a3, vv.x, yacc[3][0]);
            yacc[3][1] = fmaf(a3, vv.y, yacc[3][1]);
            yacc[3][2] = fmaf(a3, vv.z, yacc[3][2]);
            yacc[3][3] = fmaf(a3, vv.w, yacc[3][3]);
        }
    }

    #pragma unroll
    for (int i = 0; i < 4; i++) {
        *(float4*)(yatt + (size_t)(b*TT + t0 + tr0 + i) * CCH + h*DD + sc0) =
            make_float4(yacc[i][0], yacc[i][1], yacc[i][2], yacc[i][3]);
    }
}

// ---------------- launch ----------------
extern "C" void kernel_launch(void* const* d_in, const int* in_sizes, int n_in,
                              void* d_out, int out_size)
{
    const float* x      = (const float*)d_in[0];
    /* d_in[1] = dist_matrix : UNUSED by reference */
    const float* coul   = (const float*)d_in[2];
    const float* ln1g   = (const float*)d_in[3];
    const float* ln1b   = (const float*)d_in[4];
    const float* w_attn = (const float*)d_in[5];
    const float* b_attn = (const float*)d_in[6];
    const float* w_self = (const float*)d_in[7];
    const float* b_self = (const float*)d_in[8];
    const float* w_proj = (const float*)d_in[9];
    const float* b_proj = (const float*)d_in[10];
    const float* ln2g   = (const float*)d_in[11];
    const float* ln2b   = (const float*)d_in[12];
    const float* w_fc   = (const float*)d_in[13];
    const float* b_fc   = (const float*)d_in[14];
    const float* w_fcp  = (const float*)d_in[15];
    const float* b_fcp  = (const float*)d_in[16];
    float* out = (float*)d_out;

    float *h, *qkvp, *attp, *yp, *y2p, *h2p, *fcp;
    cudaGetSymbolAddress((void**)&h,    g_h);
    cudaGetSymbolAddress((void**)&qkvp, g_qkv);
    cudaGetSymbolAddress((void**)&attp, g_att);
    cudaGetSymbolAddress((void**)&yp,   g_y);
    cudaGetSymbolAddress((void**)&y2p,  g_y2);
    cudaGetSymbolAddress((void**)&h2p,  g_h2);
    cudaGetSymbolAddress((void**)&fcp,  g_fc);

    const int ATTN_SMEM = 4 * 64 * 68 * 4;   // 69632 B
    cudaFuncSetAttribute(attn_kernel, cudaFuncAttributeMaxDynamicSharedMemorySize, ATTN_SMEM);

    dim3 blk(256);
    // 1) h = LN1(x)
    ln_kernel<<<NROWS, 128>>>(x, ln1g, ln1b, h);
    // 2) qkv = h @ w_attn + b_attn           [4096 x 1536]
    sgemm_kernel<false,false><<<dim3(12,32), blk>>>(h, w_attn, b_attn, nullptr, qkvp, NROWS, C3, CCH);
    // 3) att = fused sigmoid-attention
    attn_kernel<<<dim3(TT/64, BB*HH), blk, ATTN_SMEM>>>(qkvp, coul, attp);
    // 4) y = att + h @ w_self + b_self       [4096 x 512]
    sgemm_kernel<true,false><<<dim3(4,32), blk>>>(h, w_self, b_self, attp, yp, NROWS, CCH, CCH);
    // 5) y2 = y @ w_proj + b_proj            [4096 x 512]
    sgemm_kernel<false,false><<<dim3(4,32), blk>>>(yp, w_proj, b_proj, nullptr, y2p, NROWS, CCH, CCH);
    // 6) h2 = LN2(y2)
    ln_kernel<<<NROWS, 128>>>(y2p, ln2g, ln2b, h2p);
    // 7) fc = gelu(h2 @ w_fc + b_fc)         [4096 x 2048]
    sgemm_kernel<false,true><<<dim3(16,32), blk>>>(h2p, w_fc, b_fc, nullptr, fcp, NROWS, 4*CCH, CCH);
    // 8) out = fc @ w_fc_proj + b_fc_proj    [4096 x 512]
    sgemm_kernel<false,false><<<dim3(4,32), blk>>>(fcp, w_fcp, b_fcp, nullptr, out, NROWS, CCH, 4*CCH);
}

// round 2
// speedup vs baseline: 2.7733x; 2.7733x over previous
#include <cuda_runtime.h>
#include <math.h>

// Problem constants
#define BB 2
#define TT 2048
#define CCH 512
#define HH 8
#define DD 64
#define NROWS (BB*TT)   // 4096
#define C3 (3*CCH)      // 1536

// ---------------- scratch ----------------
__device__ float g_h  [NROWS*CCH];
__device__ float g_qkv[NROWS*C3];
__device__ float g_att[NROWS*CCH];
__device__ float g_y  [NROWS*CCH];
__device__ float g_y2 [NROWS*CCH];
__device__ float g_h2 [NROWS*CCH];
__device__ float g_fc [NROWS*4*CCH];

// ---------------- helpers ----------------
__device__ __forceinline__ float cvt_tf32(float x) {
    unsigned u; asm("cvt.rna.tf32.f32 %0, %1;" : "=r"(u) : "f"(x));
    return __uint_as_float(u);
}

__device__ __forceinline__ void mma_tf32(float& c0, float& c1, float& c2, float& c3,
                                         unsigned a0, unsigned a1, unsigned a2, unsigned a3,
                                         unsigned b0, unsigned b1) {
    asm volatile("mma.sync.aligned.m16n8k8.row.col.f32.tf32.tf32.f32 "
                 "{%0,%1,%2,%3}, {%4,%5,%6,%7}, {%8,%9}, {%0,%1,%2,%3};"
                 : "+f"(c0), "+f"(c1), "+f"(c2), "+f"(c3)
                 : "r"(a0), "r"(a1), "r"(a2), "r"(a3), "r"(b0), "r"(b1));
}

// fast sigmoid: FMA-pipe only (validated in R1, rel contribution ~2e-5)
__device__ __forceinline__ float sigmoid_fast(float x) {
    float t = x * -1.4426950408889634f;
    t = fminf(fmaxf(t, -20.0f), 20.0f);
    float fi = floorf(t);
    float f  = t - fi;
    float p = 1.5403530393e-4f;
    p = fmaf(p, f, 1.3333558146e-3f);
    p = fmaf(p, f, 9.6181291076e-3f);
    p = fmaf(p, f, 5.5504108664e-2f);
    p = fmaf(p, f, 2.4022650696e-1f);
    p = fmaf(p, f, 6.9314718056e-1f);
    p = fmaf(p, f, 1.0f);
    float r = __int_as_float(((int)fi + 127) << 23) * p;
    float a = 1.0f + r;
    float y = __int_as_float(0x7EF127EA - __float_as_int(a));
    y = y * (2.0f - a * y);
    y = y * (2.0f - a * y);
    y = y * (2.0f - a * y);
    return y;
}

// ---------------- LayerNorm ----------------
__global__ __launch_bounds__(128) void ln_kernel(const float* __restrict__ x,
                                                 const float* __restrict__ g,
                                                 const float* __restrict__ bta,
                                                 float* __restrict__ out)
{
    int row = blockIdx.x;
    int t = threadIdx.x;
    const float4* xr = (const float4*)(x + (size_t)row * CCH);
    float4 v = xr[t];
    float s  = v.x + v.y + v.z + v.w;
    float s2 = v.x*v.x + v.y*v.y + v.z*v.z + v.w*v.w;
    #pragma unroll
    for (int o = 16; o; o >>= 1) {
        s  += __shfl_xor_sync(0xffffffffu, s,  o);
        s2 += __shfl_xor_sync(0xffffffffu, s2, o);
    }
    __shared__ float ss[4], ss2[4];
    int w = t >> 5, l = t & 31;
    if (l == 0) { ss[w] = s; ss2[w] = s2; }
    __syncthreads();
    s  = ss[0]  + ss[1]  + ss[2]  + ss[3];
    s2 = ss2[0] + ss2[1] + ss2[2] + ss2[3];
    float m   = s  * (1.0f/512.0f);
    float var = s2 * (1.0f/512.0f) - m*m;
    float r   = rsqrtf(var + 1e-5f);
    float4 gv = ((const float4*)g)[t];
    float4 bv = ((const float4*)bta)[t];
    float4 o4;
    o4.x = (v.x - m) * r * gv.x + bv.x;
    o4.y = (v.y - m) * r * gv.y + bv.y;
    o4.z = (v.z - m) * r * gv.z + bv.z;
    o4.w = (v.w - m) * r * gv.w + bv.w;
    ((float4*)(out + (size_t)row * CCH))[t] = o4;
}

// ---------------- TF32 tensor-core GEMM ----------------
// C = A[MxK] @ W[KxN] + bias (+addend) (+gelu)
// BM=128 BN=128 BK=32, 256 thr, warp tile 64x32 (mt=4 m16, nt=4 n8).
// As [2][128][36] (bank = 4*gid+tig, conflict-free), Bs [2][32][136] (bank = 8*tig+gid).
#define G_AS_STRIDE 36
#define G_BS_STRIDE 136
#define G_AS_SZ (128*G_AS_STRIDE)
#define G_BS_SZ (32*G_BS_STRIDE)
#define G_SMEM ((2*G_AS_SZ + 2*G_BS_SZ)*4)

template<bool HAS_ADD, bool GELU_EPI>
__global__ __launch_bounds__(256) void gemm_tf32(
    const float* __restrict__ A, const float* __restrict__ W,
    const float* __restrict__ bias, const float* __restrict__ addm,
    float* __restrict__ Cmat, int M, int N, int K)
{
    extern __shared__ float sh[];
    float* As = sh;
    float* Bs = sh + 2*G_AS_SZ;

    const int tid  = threadIdx.x;
    const int warp = tid >> 5, lane = tid & 31;
    const int gid  = lane >> 2, tig = lane & 3;
    const int wm   = (warp >> 2) * 64;
    const int wn   = (warp & 3) * 32;
    const int bm   = blockIdx.y * 128, bn = blockIdx.x * 128;

    const int ar = tid >> 3;            // + i*32
    const int ac = (tid & 7) * 4;
    const int br = tid >> 5;            // + i*8
    const int bc = (tid & 31) * 4;

    const float* Ag = A + (size_t)bm * K;
    const float* Wg = W + bn;

    float4 ra[4], rb[4];
    float acc[4][4][4];
    #pragma unroll
    for (int i = 0; i < 4; i++)
        #pragma unroll
        for (int j = 0; j < 4; j++)
            { acc[i][j][0]=0.f; acc[i][j][1]=0.f; acc[i][j][2]=0.f; acc[i][j][3]=0.f; }

    const int nk = K >> 5;

    // prologue load
    #pragma unroll
    for (int i = 0; i < 4; i++)
        ra[i] = *(const float4*)(Ag + (size_t)(ar + i*32) * K + ac);
    #pragma unroll
    for (int i = 0; i < 4; i++)
        rb[i] = *(const float4*)(Wg + (size_t)(br + i*8) * N + bc);
    {   // STS buf 0
        #pragma unroll
        for (int i = 0; i < 4; i++) {
            float* p = As + (ar + i*32)*G_AS_STRIDE + ac;
            p[0]=cvt_tf32(ra[i].x); p[1]=cvt_tf32(ra[i].y);
            p[2]=cvt_tf32(ra[i].z); p[3]=cvt_tf32(ra[i].w);
        }
        #pragma unroll
        for (int i = 0; i < 4; i++) {
            float* p = Bs + (br + i*8)*G_BS_STRIDE + bc;
            p[0]=cvt_tf32(rb[i].x); p[1]=cvt_tf32(rb[i].y);
            p[2]=cvt_tf32(rb[i].z); p[3]=cvt_tf32(rb[i].w);
        }
    }
    __syncthreads();

    for (int kt = 0; kt < nk; kt++) {
        if (kt + 1 < nk) {
            int k0 = (kt + 1) << 5;
            #pragma unroll
            for (int i = 0; i < 4; i++)
                ra[i] = *(const float4*)(Ag + (size_t)(ar + i*32) * K + k0 + ac);
            #pragma unroll
            for (int i = 0; i < 4; i++)
                rb[i] = *(const float4*)(Wg + (size_t)(k0 + br + i*8) * N + bc);
        }
        const float* as = As + (kt & 1) * G_AS_SZ;
        const float* bs = Bs + (kt & 1) * G_BS_SZ;
        #pragma unroll
        for (int ks = 0; ks < 4; ks++) {
            unsigned af[4][4], bf[4][2];
            #pragma unroll
            for (int mt = 0; mt < 4; mt++) {
                const float* ap = as + (wm + mt*16 + gid)*G_AS_STRIDE + ks*8 + tig;
                af[mt][0] = __float_as_uint(ap[0]);
                af[mt][1] = __float_as_uint(ap[8*G_AS_STRIDE]);
                af[mt][2] = __float_as_uint(ap[4]);
                af[mt][3] = __float_as_uint(ap[8*G_AS_STRIDE + 4]);
            }
            #pragma unroll
            for (int nt = 0; nt < 4; nt++) {
                const float* bp = bs + (ks*8 + tig)*G_BS_STRIDE + wn + nt*8 + gid;
                bf[nt][0] = __float_as_uint(bp[0]);
                bf[nt][1] = __float_as_uint(bp[4*G_BS_STRIDE]);
            }
            #pragma unroll
            for (int mt = 0; mt < 4; mt++)
                #pragma unroll
                for (int nt = 0; nt < 4; nt++)
                    mma_tf32(acc[mt][nt][0], acc[mt][nt][1], acc[mt][nt][2], acc[mt][nt][3],
                             af[mt][0], af[mt][1], af[mt][2], af[mt][3],
                             bf[nt][0], bf[nt][1]);
        }
        if (kt + 1 < nk) {
            float* asn = As + ((kt + 1) & 1) * G_AS_SZ;
            float* bsn = Bs + ((kt + 1) & 1) * G_BS_SZ;
            #pragma unroll
            for (int i = 0; i < 4; i++) {
                float* p = asn + (ar + i*32)*G_AS_STRIDE + ac;
                p[0]=cvt_tf32(ra[i].x); p[1]=cvt_tf32(ra[i].y);
                p[2]=cvt_tf32(ra[i].z); p[3]=cvt_tf32(ra[i].w);
            }
            #pragma unroll
            for (int i = 0; i < 4; i++) {
                float* p = bsn + (br + i*8)*G_BS_STRIDE + bc;
                p[0]=cvt_tf32(rb[i].x); p[1]=cvt_tf32(rb[i].y);
                p[2]=cvt_tf32(rb[i].z); p[3]=cvt_tf32(rb[i].w);
            }
        }
        __syncthreads();
    }

    // epilogue
    #pragma unroll
    for (int mt = 0; mt < 4; mt++) {
        int r0 = bm + wm + mt*16 + gid;
        #pragma unroll
        for (int nt = 0; nt < 4; nt++) {
            int c0 = bn + wn + nt*8 + 2*tig;
            float2 bv = *(const float2*)(bias + c0);
            float v0 = acc[mt][nt][0] + bv.x;
            float v1 = acc[mt][nt][1] + bv.y;
            float v2 = acc[mt][nt][2] + bv.x;
            float v3 = acc[mt][nt][3] + bv.y;
            size_t o0 = (size_t)r0 * N + c0;
            size_t o1 = (size_t)(r0 + 8) * N + c0;
            if (HAS_ADD) {
                float2 d0 = *(const float2*)(addm + o0);
                float2 d1 = *(const float2*)(addm + o1);
                v0 += d0.x; v1 += d0.y; v2 += d1.x; v3 += d1.y;
            }
            if (GELU_EPI) {
                v0 = 0.5f * v0 * (1.0f + erff(v0 * 0.70710678118654752f));
                v1 = 0.5f * v1 * (1.0f + erff(v1 * 0.70710678118654752f));
                v2 = 0.5f * v2 * (1.0f + erff(v2 * 0.70710678118654752f));
                v3 = 0.5f * v3 * (1.0f + erff(v3 * 0.70710678118654752f));
            }
            *(float2*)(Cmat + o0) = make_float2(v0, v1);
            *(float2*)(Cmat + o1) = make_float2(v2, v3);
        }
    }
}

// ---------------- TF32 tensor-core attention ----------------
// Block: one (b,h), 128 t-rows; sweep s in 64-chunks. 8 warps x 16 t-rows.
// Qs[128][68], Ks[64][68], Vs[64][72], Ss[128][68]. All frag LDS conflict-free.
#define A_QS_STRIDE 68
#define A_KS_STRIDE 68
#define A_VS_STRIDE 72
#define A_SS_STRIDE 68
#define A_SMEM ((128*A_QS_STRIDE + 64*A_KS_STRIDE + 64*A_VS_STRIDE + 128*A_SS_STRIDE)*4)

__global__ __launch_bounds__(256) void attn_tf32(const float* __restrict__ qkv,
                                                 const float* __restrict__ coul,
                                                 float* __restrict__ yatt)
{
    extern __shared__ float sh[];
    float* Qs = sh;
    float* Ks = Qs + 128*A_QS_STRIDE;
    float* Vs = Ks + 64*A_KS_STRIDE;
    float* Ss = Vs + 64*A_VS_STRIDE;

    int bh = blockIdx.y;
    int b = bh >> 3, h = bh & 7;
    int t0 = blockIdx.x * 128;
    int tid = threadIdx.x, warp = tid >> 5, lane = tid & 31;
    int gid = lane >> 2, tig = lane & 3;

    // load Q (scaled by 1/8, tf32)
    const float* qb = qkv + (size_t)(b*TT + t0) * C3 + h*DD;
    {
        int r = tid >> 4, c = (tid & 15) * 4;
        #pragma unroll
        for (int i = 0; i < 8; i++) {
            float4 v = *(const float4*)(qb + (size_t)(r + i*16) * C3 + c);
            float* p = Qs + (r + i*16)*A_QS_STRIDE + c;
            p[0]=cvt_tf32(v.x*0.125f); p[1]=cvt_tf32(v.y*0.125f);
            p[2]=cvt_tf32(v.z*0.125f); p[3]=cvt_tf32(v.w*0.125f);
        }
    }

    float yacc[8][4];
    #pragma unroll
    for (int i = 0; i < 8; i++) { yacc[i][0]=0.f; yacc[i][1]=0.f; yacc[i][2]=0.f; yacc[i][3]=0.f; }

    const float* cb = coul + (size_t)b * TT * TT;
    const int r0 = warp*16 + gid;

    for (int s0 = 0; s0 < TT; s0 += 64) {
        __syncthreads();   // protect Ks/Vs reuse (and covers initial Q stores)
        const float* kb = qkv + (size_t)(b*TT + s0) * C3 + CCH + h*DD;
        const float* vb = kb + CCH;
        {
            int r = tid >> 4, c = (tid & 15) * 4;
            #pragma unroll
            for (int i = 0; i < 4; i++) {
                float4 kv = *(const float4*)(kb + (size_t)(r + i*16) * C3 + c);
                float4 vv = *(const float4*)(vb + (size_t)(r + i*16) * C3 + c);
                float* pk = Ks + (r + i*16)*A_KS_STRIDE + c;
                pk[0]=cvt_tf32(kv.x); pk[1]=cvt_tf32(kv.y);
                pk[2]=cvt_tf32(kv.z); pk[3]=cvt_tf32(kv.w);
                float* pv = Vs + (r + i*16)*A_VS_STRIDE + c;
                pv[0]=cvt_tf32(vv.x); pv[1]=cvt_tf32(vv.y);
                pv[2]=cvt_tf32(vv.z); pv[3]=cvt_tf32(vv.w);
            }
        }
        __syncthreads();

        // S = Q @ K^T  (warp: 16 t-rows x 64 s)
        float sacc[8][4];
        #pragma unroll
        for (int i = 0; i < 8; i++) { sacc[i][0]=0.f; sacc[i][1]=0.f; sacc[i][2]=0.f; sacc[i][3]=0.f; }
        #pragma unroll
        for (int ks = 0; ks < 8; ks++) {
            const float* ap = Qs + r0*A_QS_STRIDE + ks*8 + tig;
            unsigned a0 = __float_as_uint(ap[0]);
            unsigned a1 = __float_as_uint(ap[8*A_QS_STRIDE]);
            unsigned a2 = __float_as_uint(ap[4]);
            unsigned a3 = __float_as_uint(ap[8*A_QS_STRIDE + 4]);
            #pragma unroll
            for (int nt = 0; nt < 8; nt++) {
                const float* bp = Ks + (nt*8 + gid)*A_KS_STRIDE + ks*8 + tig;
                mma_tf32(sacc[nt][0], sacc[nt][1], sacc[nt][2], sacc[nt][3],
                         a0, a1, a2, a3,
                         __float_as_uint(bp[0]), __float_as_uint(bp[4]));
            }
        }

        // sigmoid * coulomb -> Ss (warp-private rows)
        #pragma unroll
        for (int nt = 0; nt < 8; nt++) {
            int sc = nt*8 + 2*tig;
            float2 c0 = *(const float2*)(cb + (size_t)(t0 + r0)     * TT + s0 + sc);
            float2 c1 = *(const float2*)(cb + (size_t)(t0 + r0 + 8) * TT + s0 + sc);
            float* sp = Ss + r0*A_SS_STRIDE + sc;
            sp[0]                    = cvt_tf32(sigmoid_fast(sacc[nt][0]) * c0.x);
            sp[1]                    = cvt_tf32(sigmoid_fast(sacc[nt][1]) * c0.y);
            sp[8*A_SS_STRIDE]        = cvt_tf32(sigmoid_fast(sacc[nt][2]) * c1.x);
            sp[8*A_SS_STRIDE + 1]    = cvt_tf32(sigmoid_fast(sacc[nt][3]) * c1.y);
        }
        __syncwarp();

        // Y += S @ V  (A rows are warp-private)
        #pragma unroll
        for (int ks = 0; ks < 8; ks++) {
            const float* ap = Ss + r0*A_SS_STRIDE + ks*8 + tig;
            unsigned a0 = __float_as_uint(ap[0]);
            unsigned a1 = __float_as_uint(ap[8*A_SS_STRIDE]);
            unsigned a2 = __float_as_uint(ap[4]);
            unsigned a3 = __float_as_uint(ap[8*A_SS_STRIDE + 4]);
            #pragma unroll
            for (int nt = 0; nt < 8; nt++) {
                const float* bp = Vs + (ks*8 + tig)*A_VS_STRIDE + nt*8 + gid;
                mma_tf32(yacc[nt][0], yacc[nt][1], yacc[nt][2], yacc[nt][3],
                         a0, a1, a2, a3,
                         __float_as_uint(bp[0]), __float_as_uint(bp[4*A_VS_STRIDE]));
            }
        }
    }

    // store Y
    float* ob = yatt + (size_t)(b*TT + t0 + r0) * CCH + h*DD;
    #pragma unroll
    for (int nt = 0; nt < 8; nt++) {
        int c = nt*8 + 2*tig;
        *(float2*)(ob + c)           = make_float2(yacc[nt][0], yacc[nt][1]);
        *(float2*)(ob + 8*CCH + c)   = make_float2(yacc[nt][2], yacc[nt][3]);
    }
}

// ---------------- launch ----------------
extern "C" void kernel_launch(void* const* d_in, const int* in_sizes, int n_in,
                              void* d_out, int out_size)
{
    const float* x      = (const float*)d_in[0];
    const float* coul   = (const float*)d_in[2];
    const float* ln1g   = (const float*)d_in[3];
    const float* ln1b   = (const float*)d_in[4];
    const float* w_attn = (const float*)d_in[5];
    const float* b_attn = (const float*)d_in[6];
    const float* w_self = (const float*)d_in[7];
    const float* b_self = (const float*)d_in[8];
    const float* w_proj = (const float*)d_in[9];
    const float* b_proj = (const float*)d_in[10];
    const float* ln2g   = (const float*)d_in[11];
    const float* ln2b   = (const float*)d_in[12];
    const float* w_fc   = (const float*)d_in[13];
    const float* b_fc   = (const float*)d_in[14];
    const float* w_fcp  = (const float*)d_in[15];
    const float* b_fcp  = (const float*)d_in[16];
    float* out = (float*)d_out;

    float *h, *qkvp, *attp, *yp, *y2p, *h2p, *fcp;
    cudaGetSymbolAddress((void**)&h,    g_h);
    cudaGetSymbolAddress((void**)&qkvp, g_qkv);
    cudaGetSymbolAddress((void**)&attp, g_att);
    cudaGetSymbolAddress((void**)&yp,   g_y);
    cudaGetSymbolAddress((void**)&y2p,  g_y2);
    cudaGetSymbolAddress((void**)&h2p,  g_h2);
    cudaGetSymbolAddress((void**)&fcp,  g_fc);

    cudaFuncSetAttribute(gemm_tf32<false,false>, cudaFuncAttributeMaxDynamicSharedMemorySize, G_SMEM);
    cudaFuncSetAttribute(gemm_tf32<true,false>,  cudaFuncAttributeMaxDynamicSharedMemorySize, G_SMEM);
    cudaFuncSetAttribute(gemm_tf32<false,true>,  cudaFuncAttributeMaxDynamicSharedMemorySize, G_SMEM);
    cudaFuncSetAttribute(attn_tf32,              cudaFuncAttributeMaxDynamicSharedMemorySize, A_SMEM);

    dim3 blk(256);
    // 1) h = LN1(x)
    ln_kernel<<<NROWS, 128>>>(x, ln1g, ln1b, h);
    // 2) qkv = h @ w_attn + b_attn
    gemm_tf32<false,false><<<dim3(12,32), blk, G_SMEM>>>(h, w_attn, b_attn, nullptr, qkvp, NROWS, C3, CCH);
    // 3) fused sigmoid-attention
    attn_tf32<<<dim3(TT/128, BB*HH), blk, A_SMEM>>>(qkvp, coul, attp);
    // 4) y = att + h @ w_self + b_self
    gemm_tf32<true,false><<<dim3(4,32), blk, G_SMEM>>>(h, w_self, b_self, attp, yp, NROWS, CCH, CCH);
    // 5) y2 = y @ w_proj + b_proj
    gemm_tf32<false,false><<<dim3(4,32), blk, G_SMEM>>>(yp, w_proj, b_proj, nullptr, y2p, NROWS, CCH, CCH);
    // 6) h2 = LN2(y2)
    ln_kernel<<<NROWS, 128>>>(y2p, ln2g, ln2b, h2p);
    // 7) fc = gelu(h2 @ w_fc + b_fc)
    gemm_tf32<false,true><<<dim3(16,32), blk, G_SMEM>>>(h2p, w_fc, b_fc, nullptr, fcp, NROWS, 4*CCH, CCH);
    // 8) out = fc @ w_fc_proj + b_fc_proj
    gemm_tf32<false,false><<<dim3(4,32), blk, G_SMEM>>>(fcp, w_fcp, b_fcp, nullptr, out, NROWS, CCH, 4*CCH);
}